// round 13
// baseline (speedup 1.0000x reference)
#include <cuda_runtime.h>
#include <cuda_bf16.h>
#include <cuda_fp16.h>
#include <math_constants.h>
#include <cstdint>

#define LL 768
#define HH 8
#define EE 64
#define NH 32
#define DD 192
#define BQ 64
#define NTILE 12
#define NITEMS 384          // 12 l-tiles x 32 nh
#define GRID_ATTN 304
#define KSTR 200            // padded smem row stride (fp16 elements)
#define VSTR 72             // fp16 elements per V^T smem row

// ---------------- scratch (device globals; no allocs) ----------------
// d-layout: d = e for gate channel (0..63); d = 64+2e (cos), 65+2e (sin).
__device__ __half        g_Q[(size_t)NH * LL * DD];     // Q' fp16 single
__device__ __half        g_Khi[(size_t)NH * LL * DD];   // K' fp16 hi
__device__ __half        g_Klo[(size_t)NH * LL * DD];   // K' fp16 lo (residual)
__device__ __half        g_V[(size_t)NH * EE * LL];     // V^T fp16 [nh][e][s]
__device__ unsigned int  g_ctr;

// m16n8k16 row.col fp16 MMA, f32 accumulate
__device__ __forceinline__ void mma_f16(float* c, const uint32_t* a, uint32_t b0, uint32_t b1) {
    asm volatile("mma.sync.aligned.m16n8k16.row.col.f32.f16.f16.f32 "
                 "{%0,%1,%2,%3}, {%4,%5,%6,%7}, {%8,%9}, {%0,%1,%2,%3};"
                 : "+f"(c[0]), "+f"(c[1]), "+f"(c[2]), "+f"(c[3])
                 : "r"(a[0]), "r"(a[1]), "r"(a[2]), "r"(a[3]), "r"(b0), "r"(b1));
}

__device__ __forceinline__ uint32_t smem_u32(const void* p) {
    uint32_t a;
    asm("{ .reg .u64 t; cvta.to.shared.u64 t, %1; cvt.u32.u64 %0, t; }" : "=r"(a) : "l"(p));
    return a;
}

#define CP16(dst, src) asm volatile("cp.async.cg.shared.global [%0], [%1], 16;" :: "r"(dst), "l"(src))
#define CP_COMMIT()    asm volatile("cp.async.commit_group;" ::: "memory")
#define CP_WAIT0()     asm volatile("cp.async.wait_group 0;" ::: "memory")

__device__ __forceinline__ uint32_t pack_h2(float x, float y) {
    __half2 h = __floats2half2_rn(x, y);
    return *(uint32_t*)&h;
}
// fp16 hi/lo 2-term split of a float pair
__device__ __forceinline__ uint32_t pack_h2_hilo(float x, float y, uint32_t& lo) {
    __half2 h = __floats2half2_rn(x, y);
    __half2 l = __floats2half2_rn(x - __half2float(h.x), y - __half2float(h.y));
    lo = *(uint32_t*)&l;
    return *(uint32_t*)&h;
}

// ---------------------------------------------------------------------------
// prep (fused): blockIdx.x < 48 -> Q'/K' build; else -> V transpose (fp16).
// ---------------------------------------------------------------------------
__global__ void prep_kernel(const float* __restrict__ q, const float* __restrict__ k,
                            const float* __restrict__ values,
                            const float* __restrict__ freqs, const float* __restrict__ offsets,
                            const float* __restrict__ gains, const float* __restrict__ gate) {
    const int nh = blockIdx.y;
    const int n = nh >> 3, h = nh & 7;

    if (blockIdx.x < 48) {
        if (blockIdx.x == 0 && blockIdx.y == 0 && threadIdx.x == 0)
            g_ctr = GRID_ATTN;                // seed attn work queue

        int e  = threadIdx.x & 63;
        int j  = threadIdx.x >> 6;            // 0..3
        int l0 = blockIdx.x * 16 + j * 4;
        int he = h * 64 + e;

        float fr  = freqs[he];
        float f   = 0.5f / (1.0f + __expf(-fr));
        float off = offsets[he];
        float gn  = gains[he];
        float g   = (gn > 8.0f) ? gn : __logf(1.0f + __expf(gn));
        float gt  = gate[he];
        float c   = (1.0f - gt) * g * g;

        float lf    = (float)l0;
        float fl    = f * lf;
        float resid = fmaf(f, lf, -fl);
        float frac  = (fl - floorf(fl)) + resid;
        const float TWO_PI = 6.28318530717958647692f;
        float phk   = TWO_PI * frac;
        float argq  = phk + off;
        float cq = __cosf(argq), sq = __sinf(argq);
        float ck = __cosf(phk),  sk = __sinf(phk);
        float dph = TWO_PI * f;
        float cF = __cosf(dph), sF = __sinf(dph);

        #pragma unroll
        for (int dl = 0; dl < 4; dl++) {
            int l = l0 + dl;
            size_t qi = ((size_t)(n * LL + l) * HH + h) * EE + e;
            float qv = q[qi] * 0.125f;        // softmax temp folded into Q'
            float kv = k[qi];

            size_t base = ((size_t)nh * LL + l) * DD;
            {   // gate channel (d = e)
                g_Q[base + e] = __float2half_rn(qv * gt);
                __half khi = __float2half_rn(kv);
                g_Khi[base + e] = khi;
                g_Klo[base + e] = __float2half_rn(kv - __half2float(khi));
            }
            {   // cos/sin channels (d = 64+2e, 65+2e)
                float qc = qv * c;
                *(uint32_t*)(g_Q + base + 64 + 2 * e) = pack_h2(qc * cq, qc * sq);
                uint32_t klo;
                uint32_t khi = pack_h2_hilo(kv * ck, kv * sk, klo);
                *(uint32_t*)(g_Khi + base + 64 + 2 * e) = khi;
                *(uint32_t*)(g_Klo + base + 64 + 2 * e) = klo;
            }
            float cq2 = cq * cF - sq * sF, sq2 = sq * cF + cq * sF;
            float ck2 = ck * cF - sk * sF, sk2 = sk * cF + ck * sF;
            cq = cq2; sq = sq2; ck = ck2; sk = sk2;
        }
    } else {
        __shared__ float sm[64 * 65];
        int t = blockIdx.x - 48;
        int s0 = t * 64;

        #pragma unroll
        for (int i = 0; i < 16; i++) {
            int idx = threadIdx.x + i * 256;
            int r = idx >> 6, e = idx & 63;
            sm[e * 65 + r] = values[((size_t)(n * LL + s0 + r) * HH + h) * EE + e];
        }
        __syncthreads();

        #pragma unroll
        for (int i = 0; i < 8; i++) {
            int pid = threadIdx.x + i * 256;
            int e = pid >> 5, s2 = pid & 31;
            size_t o = ((size_t)nh * EE + e) * LL + s0 + 2 * s2;
            *(uint32_t*)(g_V + o) = pack_h2(sm[e * 65 + 2 * s2], sm[e * 65 + 2 * s2 + 1]);
        }
    }
}

// ---------------------------------------------------------------------------
// attn: persistent work-queue flash attention, all-fp16 HMMA.
// QK: 2-product (Qf16 x (Khi + Klo)); AV: single product (P,V fp16).
// cp.async pipelined exactly as the proven R8/R12 structure.
// ---------------------------------------------------------------------------
__global__ __launch_bounds__(128)
void attn_kernel(const float* __restrict__ mask, const float* __restrict__ keylen,
                 float* __restrict__ out) {
    extern __shared__ __half smem[];
    __half* sKhi = smem;                              // [64][KSTR]
    __half* sKlo = smem + 64 * KSTR;
    __half* sV   = smem + 2 * 64 * KSTR;              // [2][64][VSTR]

    const int tid  = threadIdx.x;
    const int w    = tid >> 5;
    const int lane = tid & 31;
    const int g    = lane >> 2, t = lane & 3;

    const uint32_t bKhi = smem_u32(sKhi);
    const uint32_t bKlo = smem_u32(sKlo);
    const uint32_t bV   = smem_u32(sV);

    unsigned item = blockIdx.x;
    while (item < NITEMS) {
        const int nh = (int)(item / NTILE);
        const int lt = (int)(item % NTILE);
        const int nb = nh >> 3, h = nh & 7;
        const int l0 = lt * BQ;
        const int row0 = l0 + w * 16 + g;

        const uint4* gKhiB = (const uint4*)(g_Khi + (size_t)nh * LL * DD);
        const uint4* gKloB = (const uint4*)(g_Klo + (size_t)nh * LL * DD);

        // issue cp.async group for tile it2 (K single buf, V buf vb)
        auto issue_tile = [&](int it2, int vb) {
            const uint4* gH = gKhiB + (size_t)it2 * 64 * DD / 8;
            const uint4* gL = gKloB + (size_t)it2 * 64 * DD / 8;
            #pragma unroll
            for (int i = 0; i < 12; i++) {
                int idx = tid + i * 128;
                int r = idx / 24, c = idx % 24;
                uint32_t off = (uint32_t)(r * KSTR + c * 8) * 2u;
                CP16(bKhi + off, gH + idx);
                CP16(bKlo + off, gL + idx);
            }
            #pragma unroll
            for (int i = 0; i < 4; i++) {
                int idx = tid + i * 128;
                int r = idx / 8, c = idx % 8;
                size_t go = ((size_t)nh * EE + r) * LL + it2 * 64 + c * 8;
                uint32_t off = (uint32_t)(vb * 64 * VSTR + r * VSTR + c * 8) * 2u;
                CP16(bV + off, (const uint4*)(g_V + go));
            }
        };

        issue_tile(0, 0);
        CP_COMMIT();

        // ---- Q fragments (fp16 single; register resident for this item) ----
        uint32_t aQ[12][4];
        {
            const __half* qp = g_Q + ((size_t)nh * LL + row0) * DD;
            #pragma unroll
            for (int c = 0; c < 12; c++) {
                int d0 = c * 16 + 2 * t;
                aQ[c][0] = *(const uint32_t*)(qp + d0);
                aQ[c][1] = *(const uint32_t*)(qp + 8 * DD + d0);
                aQ[c][2] = *(const uint32_t*)(qp + d0 + 8);
                aQ[c][3] = *(const uint32_t*)(qp + 8 * DD + d0 + 8);
            }
        }

        float O[8][4];
        #pragma unroll
        for (int n = 0; n < 8; n++)
            #pragma unroll
            for (int j = 0; j < 4; j++) O[n][j] = 0.f;
        float m0 = -CUDART_INF_F, m1 = -CUDART_INF_F, ls0 = 0.f, ls1 = 0.f;

        const float* mrow0b = mask + (size_t)row0 * LL;
        const float* mrow1b = mrow0b + 8 * LL;
        const float* klb    = keylen + (size_t)nb * LL;

        for (int it = 0; it < NTILE; it++) {
            CP_WAIT0();
            __syncthreads();

            // ---- S = Q' K'^T : c outer, staged B frags, 2 fp16 products ----
            float S[8][4];
            #pragma unroll
            for (int n = 0; n < 8; n++)
                #pragma unroll
                for (int j = 0; j < 4; j++) S[n][j] = 0.f;

            #pragma unroll
            for (int c = 0; c < 12; c++) {
                uint32_t bh[8][2], bl[8][2];
                #pragma unroll
                for (int n = 0; n < 8; n++) {
                    const __half* kh = sKhi + (n * 8 + g) * KSTR + 2 * t + c * 16;
                    const __half* kl = sKlo + (n * 8 + g) * KSTR + 2 * t + c * 16;
                    bh[n][0] = *(const uint32_t*)(kh);
                    bh[n][1] = *(const uint32_t*)(kh + 8);
                    bl[n][0] = *(const uint32_t*)(kl);
                    bl[n][1] = *(const uint32_t*)(kl + 8);
                }
                #pragma unroll
                for (int n = 0; n < 8; n++) mma_f16(S[n], aQ[c], bh[n][0], bh[n][1]);
                #pragma unroll
                for (int n = 0; n < 8; n++) mma_f16(S[n], aQ[c], bl[n][0], bl[n][1]);
            }
            __syncthreads();   // all warps done reading K smem

            if (it + 1 < NTILE) issue_tile(it + 1, (it + 1) & 1);
            CP_COMMIT();

            // ---- bias: 0.125 * (mask + keylen) ----
            {
                const float* mr0 = mrow0b + it * 64;
                const float* mr1 = mrow1b + it * 64;
                const float* kl  = klb + it * 64;
                #pragma unroll
                for (int n = 0; n < 8; n++) {
                    int sc = n * 8 + 2 * t;
                    float2 a0 = *(const float2*)(mr0 + sc);
                    float2 a1 = *(const float2*)(mr1 + sc);
                    float2 kk = *(const float2*)(kl + sc);
                    S[n][0] += 0.125f * (a0.x + kk.x);
                    S[n][1] += 0.125f * (a0.y + kk.y);
                    S[n][2] += 0.125f * (a1.x + kk.x);
                    S[n][3] += 0.125f * (a1.y + kk.y);
                }
            }

            // ---- online softmax (rows quad-local) ----
            float mx0 = S[0][0], mx1 = S[0][2];
            #pragma unroll
            for (int n = 0; n < 8; n++) {
                mx0 = fmaxf(mx0, fmaxf(S[n][0], S[n][1]));
                mx1 = fmaxf(mx1, fmaxf(S[n][2], S[n][3]));
            }
            mx0 = fmaxf(mx0, __shfl_xor_sync(0xffffffffu, mx0, 1));
            mx0 = fmaxf(mx0, __shfl_xor_sync(0xffffffffu, mx0, 2));
            mx1 = fmaxf(mx1, __shfl_xor_sync(0xffffffffu, mx1, 1));
            mx1 = fmaxf(mx1, __shfl_xor_sync(0xffffffffu, mx1, 2));
            float m0n = fmaxf(m0, mx0), m1n = fmaxf(m1, mx1);
            float c0 = __expf(m0 - m0n), c1 = __expf(m1 - m1n);
            m0 = m0n; m1 = m1n;
            float s0 = 0.f, s1 = 0.f;
            #pragma unroll
            for (int n = 0; n < 8; n++) {
                S[n][0] = __expf(S[n][0] - m0n);
                S[n][1] = __expf(S[n][1] - m0n);
                S[n][2] = __expf(S[n][2] - m1n);
                S[n][3] = __expf(S[n][3] - m1n);
                s0 += S[n][0] + S[n][1];
                s1 += S[n][2] + S[n][3];
                O[n][0] *= c0; O[n][1] *= c0;
                O[n][2] *= c1; O[n][3] *= c1;
            }
            s0 += __shfl_xor_sync(0xffffffffu, s0, 1);
            s0 += __shfl_xor_sync(0xffffffffu, s0, 2);
            s1 += __shfl_xor_sync(0xffffffffu, s1, 1);
            s1 += __shfl_xor_sync(0xffffffffu, s1, 2);
            ls0 = ls0 * c0 + s0;
            ls1 = ls1 * c1 + s1;

            // ---- P -> fp16 A-fragments (single product) ----
            uint32_t ph[4][4];
            #pragma unroll
            for (int kc = 0; kc < 4; kc++) {
                ph[kc][0] = pack_h2(S[2*kc][0],   S[2*kc][1]);
                ph[kc][1] = pack_h2(S[2*kc][2],   S[2*kc][3]);
                ph[kc][2] = pack_h2(S[2*kc+1][0], S[2*kc+1][1]);
                ph[kc][3] = pack_h2(S[2*kc+1][2], S[2*kc+1][3]);
            }

            // ---- O += P V : kc outer, staged V frags, single fp16 product ----
            const __half* vb = sV + (it & 1) * 64 * VSTR;
            #pragma unroll
            for (int kc = 0; kc < 4; kc++) {
                uint32_t vh[8][2];
                #pragma unroll
                for (int n = 0; n < 8; n++) {
                    const __half* vhp = vb + (n * 8 + g) * VSTR + 2 * t + kc * 16;
                    vh[n][0] = *(const uint32_t*)(vhp);
                    vh[n][1] = *(const uint32_t*)(vhp + 8);
                }
                #pragma unroll
                for (int n = 0; n < 8; n++) mma_f16(O[n], ph[kc], vh[n][0], vh[n][1]);
            }
        }

        // ---- epilogue for this item ----
        float inv0 = 1.0f / ls0, inv1 = 1.0f / ls1;
        float* o0 = out + ((size_t)(nb * LL + row0) * HH + h) * EE;
        float* o1 = o0 + 8 * HH * EE;
        #pragma unroll
        for (int n = 0; n < 8; n++) {
            int e = n * 8 + 2 * t;
            *(float2*)(o0 + e) = make_float2(O[n][0] * inv0, O[n][1] * inv0);
            *(float2*)(o1 + e) = make_float2(O[n][2] * inv1, O[n][3] * inv1);
        }

        // ---- next work item ----
        __shared__ unsigned s_item;
        __syncthreads();
        if (tid == 0) s_item = atomicAdd(&g_ctr, 1u);
        __syncthreads();
        item = s_item;
    }
}

// ---------------------------------------------------------------------------
extern "C" void kernel_launch(void* const* d_in, const int* in_sizes, int n_in,
                              void* d_out, int out_size) {
    const float* queries = (const float*)d_in[0];
    const float* keys    = (const float*)d_in[1];
    const float* values  = (const float*)d_in[2];
    const float* mask    = (const float*)d_in[3];
    const float* keylen  = (const float*)d_in[4];
    const float* freqs   = (const float*)d_in[5];
    const float* offsets = (const float*)d_in[6];
    const float* gains   = (const float*)d_in[7];
    const float* gate    = (const float*)d_in[8];
    float* out = (float*)d_out;

    prep_kernel<<<dim3(48 + NTILE, NH), 256>>>(queries, keys, values,
                                               freqs, offsets, gains, gate);

    const int smem = (2 * 64 * KSTR + 2 * 64 * VSTR) * 2;   // 69632 B
    cudaFuncSetAttribute(attn_kernel, cudaFuncAttributeMaxDynamicSharedMemorySize, smem);
    attn_kernel<<<GRID_ATTN, 128, smem>>>(mask, keylen, out);
}

// round 14
// speedup vs baseline: 1.0666x; 1.0666x over previous
#include <cuda_runtime.h>
#include <cuda_bf16.h>
#include <cuda_fp16.h>
#include <math_constants.h>
#include <cstdint>

#define LL 768
#define HH 8
#define EE 64
#define NH 32
#define DD 192
#define BQ 64
#define NTILE 12
#define NITEMS 384          // 12 l-tiles x 32 nh
#define GRID_ATTN 304
#define KSTR 196            // padded smem row stride (fp32 words): 196%32=4 -> conflict-free
#define VSTR 72             // fp16 elements per V^T smem row

// ---------------- scratch (device globals; no allocs) ----------------
// d-layout: d = e for gate channel (0..63); d = 64+2e (cos), 65+2e (sin).
__device__ float         g_Q[(size_t)NH * LL * DD];     // Q' tf32 (in fp32 storage)
__device__ float         g_K[(size_t)NH * LL * DD];     // K' tf32
__device__ __half        g_V[(size_t)NH * EE * LL];     // V^T fp16 [nh][e][s]
__device__ unsigned int  g_ctr;

// m16n8k8 row.col tf32 MMA, f32 accumulate (QK path)
__device__ __forceinline__ void mma_tf32(float* c, const uint32_t* a, uint32_t b0, uint32_t b1) {
    asm volatile("mma.sync.aligned.m16n8k8.row.col.f32.tf32.tf32.f32 "
                 "{%0,%1,%2,%3}, {%4,%5,%6,%7}, {%8,%9}, {%0,%1,%2,%3};"
                 : "+f"(c[0]), "+f"(c[1]), "+f"(c[2]), "+f"(c[3])
                 : "r"(a[0]), "r"(a[1]), "r"(a[2]), "r"(a[3]), "r"(b0), "r"(b1));
}
// m16n8k16 row.col fp16 MMA, f32 accumulate (AV path)
__device__ __forceinline__ void mma_f16(float* c, const uint32_t* a, uint32_t b0, uint32_t b1) {
    asm volatile("mma.sync.aligned.m16n8k16.row.col.f32.f16.f16.f32 "
                 "{%0,%1,%2,%3}, {%4,%5,%6,%7}, {%8,%9}, {%0,%1,%2,%3};"
                 : "+f"(c[0]), "+f"(c[1]), "+f"(c[2]), "+f"(c[3])
                 : "r"(a[0]), "r"(a[1]), "r"(a[2]), "r"(a[3]), "r"(b0), "r"(b1));
}

__device__ __forceinline__ uint32_t smem_u32(const void* p) {
    uint32_t a;
    asm("{ .reg .u64 t; cvta.to.shared.u64 t, %1; cvt.u32.u64 %0, t; }" : "=r"(a) : "l"(p));
    return a;
}

#define CP16(dst, src) asm volatile("cp.async.cg.shared.global [%0], [%1], 16;" :: "r"(dst), "l"(src))
#define CP_COMMIT()    asm volatile("cp.async.commit_group;" ::: "memory")
#define CP_WAIT0()     asm volatile("cp.async.wait_group 0;" ::: "memory")

__device__ __forceinline__ float to_tf32(float x) {
    float r;
    asm("cvt.rna.tf32.f32 %0, %1;" : "=f"(r) : "f"(x));
    return r;
}
__device__ __forceinline__ uint32_t pack_h2(float x, float y) {
    __half2 h = __floats2half2_rn(x, y);
    return *(uint32_t*)&h;
}

// ---------------------------------------------------------------------------
// prep (fused): blockIdx.x < 48 -> Q'/K' tf32 build; else -> V transpose (fp16).
// ---------------------------------------------------------------------------
__global__ void prep_kernel(const float* __restrict__ q, const float* __restrict__ k,
                            const float* __restrict__ values,
                            const float* __restrict__ freqs, const float* __restrict__ offsets,
                            const float* __restrict__ gains, const float* __restrict__ gate) {
    const int nh = blockIdx.y;
    const int n = nh >> 3, h = nh & 7;

    if (blockIdx.x < 48) {
        if (blockIdx.x == 0 && blockIdx.y == 0 && threadIdx.x == 0)
            g_ctr = GRID_ATTN;                // seed attn work queue

        int e  = threadIdx.x & 63;
        int j  = threadIdx.x >> 6;            // 0..3
        int l0 = blockIdx.x * 16 + j * 4;
        int he = h * 64 + e;

        float fr  = freqs[he];
        float f   = 0.5f / (1.0f + __expf(-fr));
        float off = offsets[he];
        float gn  = gains[he];
        float g   = (gn > 8.0f) ? gn : __logf(1.0f + __expf(gn));
        float gt  = gate[he];
        float c   = (1.0f - gt) * g * g;

        float lf    = (float)l0;
        float fl    = f * lf;
        float resid = fmaf(f, lf, -fl);
        float frac  = (fl - floorf(fl)) + resid;
        const float TWO_PI = 6.28318530717958647692f;
        float phk   = TWO_PI * frac;
        float argq  = phk + off;
        float cq = __cosf(argq), sq = __sinf(argq);
        float ck = __cosf(phk),  sk = __sinf(phk);
        float dph = TWO_PI * f;
        float cF = __cosf(dph), sF = __sinf(dph);

        #pragma unroll
        for (int dl = 0; dl < 4; dl++) {
            int l = l0 + dl;
            size_t qi = ((size_t)(n * LL + l) * HH + h) * EE + e;
            float qv = q[qi] * 0.125f;        // softmax temp folded into Q'
            float kv = k[qi];

            size_t base = ((size_t)nh * LL + l) * DD;
            // gate channel (d = e)
            g_Q[base + e] = to_tf32(qv * gt);
            g_K[base + e] = to_tf32(kv);
            // cos/sin channels (d = 64+2e, 65+2e)
            float qc = qv * c;
            *(float2*)(g_Q + base + 64 + 2 * e) =
                make_float2(to_tf32(qc * cq), to_tf32(qc * sq));
            *(float2*)(g_K + base + 64 + 2 * e) =
                make_float2(to_tf32(kv * ck), to_tf32(kv * sk));

            float cq2 = cq * cF - sq * sF, sq2 = sq * cF + cq * sF;
            float ck2 = ck * cF - sk * sF, sk2 = sk * cF + ck * sF;
            cq = cq2; sq = sq2; ck = ck2; sk = sk2;
        }
    } else {
        __shared__ float sm[64 * 65];
        int t = blockIdx.x - 48;
        int s0 = t * 64;

        #pragma unroll
        for (int i = 0; i < 16; i++) {
            int idx = threadIdx.x + i * 256;
            int r = idx >> 6, e = idx & 63;
            sm[e * 65 + r] = values[((size_t)(n * LL + s0 + r) * HH + h) * EE + e];
        }
        __syncthreads();

        #pragma unroll
        for (int i = 0; i < 8; i++) {
            int pid = threadIdx.x + i * 256;
            int e = pid >> 5, s2 = pid & 31;
            size_t o = ((size_t)nh * EE + e) * LL + s0 + 2 * s2;
            *(uint32_t*)(g_V + o) = pack_h2(sm[e * 65 + 2 * s2], sm[e * 65 + 2 * s2 + 1]);
        }
    }
}

// ---------------------------------------------------------------------------
// attn: persistent work-queue flash attention.
// QK: single-product tf32 m16n8k8 (24 k-chunks x 8 n = 192 MMA/tile).
// AV: single-product fp16 m16n8k16 (32 MMA/tile).
// cp.async pipelined exactly as the proven R8/R12 structure.
// ---------------------------------------------------------------------------
__global__ __launch_bounds__(128)
void attn_kernel(const float* __restrict__ mask, const float* __restrict__ keylen,
                 float* __restrict__ out) {
    extern __shared__ float smemf[];
    float*  sK = smemf;                               // [64][KSTR] tf32
    __half* sV = (__half*)(smemf + 64 * KSTR);        // [2][64][VSTR]

    const int tid  = threadIdx.x;
    const int w    = tid >> 5;
    const int lane = tid & 31;
    const int g    = lane >> 2, t = lane & 3;

    const uint32_t bK = smem_u32(sK);
    const uint32_t bV = smem_u32(sV);

    unsigned item = blockIdx.x;
    while (item < NITEMS) {
        const int nh = (int)(item / NTILE);
        const int lt = (int)(item % NTILE);
        const int nb = nh >> 3, h = nh & 7;
        const int l0 = lt * BQ;
        const int row0 = l0 + w * 16 + g;

        const float* gKB = g_K + (size_t)nh * LL * DD;

        // issue cp.async group for tile it2 (K single buf, V buf vb)
        auto issue_tile = [&](int it2, int vb) {
            const float* gKt = gKB + (size_t)it2 * 64 * DD;
            #pragma unroll
            for (int i = 0; i < 24; i++) {
                int idx = tid + i * 128;          // 3072 x 16B = 48KB
                int r = idx / 48, c = idx % 48;
                uint32_t off = (uint32_t)(r * KSTR + c * 4) * 4u;
                CP16(bK + off, (const uint4*)(gKt + (size_t)r * DD + c * 4));
            }
            #pragma unroll
            for (int i = 0; i < 4; i++) {
                int idx = tid + i * 128;
                int r = idx / 8, c = idx % 8;
                size_t go = ((size_t)nh * EE + r) * LL + it2 * 64 + c * 8;
                uint32_t off = (uint32_t)(vb * 64 * VSTR + r * VSTR + c * 8) * 2u;
                CP16(bV + off, (const uint4*)(g_V + go));
            }
        };

        issue_tile(0, 0);
        CP_COMMIT();

        // ---- Q fragments (tf32; register resident for this item) ----
        // m16n8k8 A layout: a0=(g, t), a1=(g+8, t), a2=(g, t+4), a3=(g+8, t+4)
        uint32_t aQ[24][4];
        {
            const uint32_t* qp = (const uint32_t*)(g_Q + ((size_t)nh * LL + row0) * DD);
            #pragma unroll
            for (int c = 0; c < 24; c++) {
                int d0 = c * 8 + t;
                aQ[c][0] = qp[d0];
                aQ[c][1] = qp[8 * DD + d0];
                aQ[c][2] = qp[d0 + 4];
                aQ[c][3] = qp[8 * DD + d0 + 4];
            }
        }

        float O[8][4];
        #pragma unroll
        for (int n = 0; n < 8; n++)
            #pragma unroll
            for (int j = 0; j < 4; j++) O[n][j] = 0.f;
        float m0 = -CUDART_INF_F, m1 = -CUDART_INF_F, ls0 = 0.f, ls1 = 0.f;

        const float* mrow0b = mask + (size_t)row0 * LL;
        const float* mrow1b = mrow0b + 8 * LL;
        const float* klb    = keylen + (size_t)nb * LL;

        for (int it = 0; it < NTILE; it++) {
            CP_WAIT0();
            __syncthreads();

            // ---- S = Q' K'^T : 24 k8-chunks x 8 n, single tf32 product ----
            float S[8][4];
            #pragma unroll
            for (int n = 0; n < 8; n++)
                #pragma unroll
                for (int j = 0; j < 4; j++) S[n][j] = 0.f;

            #pragma unroll
            for (int c = 0; c < 24; c++) {
                uint32_t bh[8][2];
                #pragma unroll
                for (int n = 0; n < 8; n++) {
                    const uint32_t* kp = (const uint32_t*)(sK + (n * 8 + g) * KSTR + c * 8);
                    bh[n][0] = kp[t];
                    bh[n][1] = kp[t + 4];
                }
                #pragma unroll
                for (int n = 0; n < 8; n++) mma_tf32(S[n], aQ[c], bh[n][0], bh[n][1]);
            }
            __syncthreads();   // all warps done reading K smem

            if (it + 1 < NTILE) issue_tile(it + 1, (it + 1) & 1);
            CP_COMMIT();

            // ---- bias: 0.125 * (mask + keylen) ----
            {
                const float* mr0 = mrow0b + it * 64;
                const float* mr1 = mrow1b + it * 64;
                const float* kl  = klb + it * 64;
                #pragma unroll
                for (int n = 0; n < 8; n++) {
                    int sc = n * 8 + 2 * t;
                    float2 a0 = *(const float2*)(mr0 + sc);
                    float2 a1 = *(const float2*)(mr1 + sc);
                    float2 kk = *(const float2*)(kl + sc);
                    S[n][0] += 0.125f * (a0.x + kk.x);
                    S[n][1] += 0.125f * (a0.y + kk.y);
                    S[n][2] += 0.125f * (a1.x + kk.x);
                    S[n][3] += 0.125f * (a1.y + kk.y);
                }
            }

            // ---- online softmax (rows quad-local) ----
            float mx0 = S[0][0], mx1 = S[0][2];
            #pragma unroll
            for (int n = 0; n < 8; n++) {
                mx0 = fmaxf(mx0, fmaxf(S[n][0], S[n][1]));
                mx1 = fmaxf(mx1, fmaxf(S[n][2], S[n][3]));
            }
            mx0 = fmaxf(mx0, __shfl_xor_sync(0xffffffffu, mx0, 1));
            mx0 = fmaxf(mx0, __shfl_xor_sync(0xffffffffu, mx0, 2));
            mx1 = fmaxf(mx1, __shfl_xor_sync(0xffffffffu, mx1, 1));
            mx1 = fmaxf(mx1, __shfl_xor_sync(0xffffffffu, mx1, 2));
            float m0n = fmaxf(m0, mx0), m1n = fmaxf(m1, mx1);
            float c0 = __expf(m0 - m0n), c1 = __expf(m1 - m1n);
            m0 = m0n; m1 = m1n;
            float s0 = 0.f, s1 = 0.f;
            #pragma unroll
            for (int n = 0; n < 8; n++) {
                S[n][0] = __expf(S[n][0] - m0n);
                S[n][1] = __expf(S[n][1] - m0n);
                S[n][2] = __expf(S[n][2] - m1n);
                S[n][3] = __expf(S[n][3] - m1n);
                s0 += S[n][0] + S[n][1];
                s1 += S[n][2] + S[n][3];
                O[n][0] *= c0; O[n][1] *= c0;
                O[n][2] *= c1; O[n][3] *= c1;
            }
            s0 += __shfl_xor_sync(0xffffffffu, s0, 1);
            s0 += __shfl_xor_sync(0xffffffffu, s0, 2);
            s1 += __shfl_xor_sync(0xffffffffu, s1, 1);
            s1 += __shfl_xor_sync(0xffffffffu, s1, 2);
            ls0 = ls0 * c0 + s0;
            ls1 = ls1 * c1 + s1;

            // ---- P -> fp16 A-fragments (single product) ----
            uint32_t ph[4][4];
            #pragma unroll
            for (int kc = 0; kc < 4; kc++) {
                ph[kc][0] = pack_h2(S[2*kc][0],   S[2*kc][1]);
                ph[kc][1] = pack_h2(S[2*kc][2],   S[2*kc][3]);
                ph[kc][2] = pack_h2(S[2*kc+1][0], S[2*kc+1][1]);
                ph[kc][3] = pack_h2(S[2*kc+1][2], S[2*kc+1][3]);
            }

            // ---- O += P V : kc outer, staged V frags, single fp16 product ----
            const __half* vb = sV + (it & 1) * 64 * VSTR;
            #pragma unroll
            for (int kc = 0; kc < 4; kc++) {
                uint32_t vh[8][2];
                #pragma unroll
                for (int n = 0; n < 8; n++) {
                    const __half* vhp = vb + (n * 8 + g) * VSTR + 2 * t + kc * 16;
                    vh[n][0] = *(const uint32_t*)(vhp);
                    vh[n][1] = *(const uint32_t*)(vhp + 8);
                }
                #pragma unroll
                for (int n = 0; n < 8; n++) mma_f16(O[n], ph[kc], vh[n][0], vh[n][1]);
            }
        }

        // ---- epilogue for this item ----
        float inv0 = 1.0f / ls0, inv1 = 1.0f / ls1;
        float* o0 = out + ((size_t)(nb * LL + row0) * HH + h) * EE;
        float* o1 = o0 + 8 * HH * EE;
        #pragma unroll
        for (int n = 0; n < 8; n++) {
            int e = n * 8 + 2 * t;
            *(float2*)(o0 + e) = make_float2(O[n][0] * inv0, O[n][1] * inv0);
            *(float2*)(o1 + e) = make_float2(O[n][2] * inv1, O[n][3] * inv1);
        }

        // ---- next work item ----
        __shared__ unsigned s_item;
        __syncthreads();
        if (tid == 0) s_item = atomicAdd(&g_ctr, 1u);
        __syncthreads();
        item = s_item;
    }
}

// ---------------------------------------------------------------------------
extern "C" void kernel_launch(void* const* d_in, const int* in_sizes, int n_in,
                              void* d_out, int out_size) {
    const float* queries = (const float*)d_in[0];
    const float* keys    = (const float*)d_in[1];
    const float* values  = (const float*)d_in[2];
    const float* mask    = (const float*)d_in[3];
    const float* keylen  = (const float*)d_in[4];
    const float* freqs   = (const float*)d_in[5];
    const float* offsets = (const float*)d_in[6];
    const float* gains   = (const float*)d_in[7];
    const float* gate    = (const float*)d_in[8];
    float* out = (float*)d_out;

    prep_kernel<<<dim3(48 + NTILE, NH), 256>>>(queries, keys, values,
                                               freqs, offsets, gains, gate);

    const int smem = 64 * KSTR * 4 + 2 * 64 * VSTR * 2;   // 68608 B
    cudaFuncSetAttribute(attn_kernel, cudaFuncAttributeMaxDynamicSharedMemorySize, smem);
    attn_kernel<<<GRID_ATTN, 128, smem>>>(mask, keylen, out);
}

// round 15
// speedup vs baseline: 1.2295x; 1.1527x over previous
#include <cuda_runtime.h>
#include <cuda_bf16.h>
#include <cuda_fp16.h>
#include <math_constants.h>
#include <cstdint>

#define LL 768
#define HH 8
#define EE 64
#define NH 32
#define DD_CS 128           // cos/sin channel dims (bf16 3-product)
#define DD_G 64             // gate channel dims (f16 single-product)
#define BQ 64
#define NTILE 12
#define NITEMS 384          // 12 l-tiles x 32 nh
#define GRID_ATTN 304
#define KSTR 136            // bf16 elems per K cos/sin smem row (272B, %128=16 -> conflict-free)
#define GSTR 72             // f16 elems per gate/V smem row (144B, %128=16)

// ---------------- scratch (device globals; no allocs) ----------------
__device__ __nv_bfloat16 g_Qhi[(size_t)NH * LL * DD_CS];   // Q' cos/sin hi
__device__ __nv_bfloat16 g_Qlo[(size_t)NH * LL * DD_CS];
__device__ __nv_bfloat16 g_Khi[(size_t)NH * LL * DD_CS];   // K' cos/sin hi
__device__ __nv_bfloat16 g_Klo[(size_t)NH * LL * DD_CS];
__device__ __half        g_Qg[(size_t)NH * LL * DD_G];     // Q' gate (f16)
__device__ __half        g_Kg[(size_t)NH * LL * DD_G];     // K' gate (f16)
__device__ __half        g_V[(size_t)NH * EE * LL];        // V^T fp16 [nh][e][s]
__device__ unsigned int  g_ctr;

// m16n8k16 row.col bf16 MMA, f32 accumulate
__device__ __forceinline__ void mma_bf16(float* c, const uint32_t* a, uint32_t b0, uint32_t b1) {
    asm volatile("mma.sync.aligned.m16n8k16.row.col.f32.bf16.bf16.f32 "
                 "{%0,%1,%2,%3}, {%4,%5,%6,%7}, {%8,%9}, {%0,%1,%2,%3};"
                 : "+f"(c[0]), "+f"(c[1]), "+f"(c[2]), "+f"(c[3])
                 : "r"(a[0]), "r"(a[1]), "r"(a[2]), "r"(a[3]), "r"(b0), "r"(b1));
}
// m16n8k16 row.col fp16 MMA, f32 accumulate
__device__ __forceinline__ void mma_f16(float* c, const uint32_t* a, uint32_t b0, uint32_t b1) {
    asm volatile("mma.sync.aligned.m16n8k16.row.col.f32.f16.f16.f32 "
                 "{%0,%1,%2,%3}, {%4,%5,%6,%7}, {%8,%9}, {%0,%1,%2,%3};"
                 : "+f"(c[0]), "+f"(c[1]), "+f"(c[2]), "+f"(c[3])
                 : "r"(a[0]), "r"(a[1]), "r"(a[2]), "r"(a[3]), "r"(b0), "r"(b1));
}

__device__ __forceinline__ uint32_t smem_u32(const void* p) {
    uint32_t a;
    asm("{ .reg .u64 t; cvta.to.shared.u64 t, %1; cvt.u32.u64 %0, t; }" : "=r"(a) : "l"(p));
    return a;
}

#define CP16(dst, src) asm volatile("cp.async.cg.shared.global [%0], [%1], 16;" :: "r"(dst), "l"(src))
#define CP_COMMIT()    asm volatile("cp.async.commit_group;" ::: "memory")
#define CP_WAIT0()     asm volatile("cp.async.wait_group 0;" ::: "memory")

__device__ __forceinline__ uint32_t pack_hi(float x, float y, uint32_t& lo) {
    __nv_bfloat162 h2;
    h2.x = __float2bfloat16(x);
    h2.y = __float2bfloat16(y);
    __nv_bfloat162 l2;
    l2.x = __float2bfloat16(x - __bfloat162float(h2.x));
    l2.y = __float2bfloat16(y - __bfloat162float(h2.y));
    lo = *(uint32_t*)&l2;
    return *(uint32_t*)&h2;
}
__device__ __forceinline__ uint32_t pack_h2(float x, float y) {
    __half2 h = __floats2half2_rn(x, y);
    return *(uint32_t*)&h;
}

// ---------------------------------------------------------------------------
// prep (fused): blockIdx.x < 48 -> Q'/K' build; else -> V transpose (fp16).
// ---------------------------------------------------------------------------
__global__ void prep_kernel(const float* __restrict__ q, const float* __restrict__ k,
                            const float* __restrict__ values,
                            const float* __restrict__ freqs, const float* __restrict__ offsets,
                            const float* __restrict__ gains, const float* __restrict__ gate) {
    const int nh = blockIdx.y;
    const int n = nh >> 3, h = nh & 7;

    if (blockIdx.x < 48) {
        if (blockIdx.x == 0 && blockIdx.y == 0 && threadIdx.x == 0)
            g_ctr = GRID_ATTN;                // seed attn work queue

        int e  = threadIdx.x & 63;
        int j  = threadIdx.x >> 6;            // 0..3
        int l0 = blockIdx.x * 16 + j * 4;
        int he = h * 64 + e;

        float fr  = freqs[he];
        float f   = 0.5f / (1.0f + __expf(-fr));
        float off = offsets[he];
        float gn  = gains[he];
        float g   = (gn > 8.0f) ? gn : __logf(1.0f + __expf(gn));
        float gt  = gate[he];
        float c   = (1.0f - gt) * g * g;

        float lf    = (float)l0;
        float fl    = f * lf;
        float resid = fmaf(f, lf, -fl);
        float frac  = (fl - floorf(fl)) + resid;
        const float TWO_PI = 6.28318530717958647692f;
        float phk   = TWO_PI * frac;
        float argq  = phk + off;
        float cq = __cosf(argq), sq = __sinf(argq);
        float ck = __cosf(phk),  sk = __sinf(phk);
        float dph = TWO_PI * f;
        float cF = __cosf(dph), sF = __sinf(dph);

        #pragma unroll
        for (int dl = 0; dl < 4; dl++) {
            int l = l0 + dl;
            size_t qi = ((size_t)(n * LL + l) * HH + h) * EE + e;
            float qv = q[qi] * 0.125f;        // softmax temp folded into Q'
            float kv = k[qi];

            size_t b64  = ((size_t)nh * LL + l) * DD_G;
            size_t b128 = ((size_t)nh * LL + l) * DD_CS;
            // gate channel: f16 single precision (error budget ~2.6e-4)
            g_Qg[b64 + e] = __float2half_rn(qv * gt);
            g_Kg[b64 + e] = __float2half_rn(kv);
            // cos/sin channels: bf16 hi/lo (exact to 2^-16)
            float qc = qv * c;
            uint32_t lo;
            uint32_t hi = pack_hi(qc * cq, qc * sq, lo);
            *(uint32_t*)(g_Qhi + b128 + 2 * e) = hi;
            *(uint32_t*)(g_Qlo + b128 + 2 * e) = lo;
            uint32_t wlo;
            uint32_t whi = pack_hi(kv * ck, kv * sk, wlo);
            *(uint32_t*)(g_Khi + b128 + 2 * e) = whi;
            *(uint32_t*)(g_Klo + b128 + 2 * e) = wlo;

            float cq2 = cq * cF - sq * sF, sq2 = sq * cF + cq * sF;
            float ck2 = ck * cF - sk * sF, sk2 = sk * cF + ck * sF;
            cq = cq2; sq = sq2; ck = ck2; sk = sk2;
        }
    } else {
        __shared__ float sm[64 * 65];
        int t = blockIdx.x - 48;
        int s0 = t * 64;

        #pragma unroll
        for (int i = 0; i < 16; i++) {
            int idx = threadIdx.x + i * 256;
            int r = idx >> 6, e = idx & 63;
            sm[e * 65 + r] = values[((size_t)(n * LL + s0 + r) * HH + h) * EE + e];
        }
        __syncthreads();

        #pragma unroll
        for (int i = 0; i < 8; i++) {
            int pid = threadIdx.x + i * 256;
            int e = pid >> 5, s2 = pid & 31;
            size_t o = ((size_t)nh * EE + e) * LL + s0 + 2 * s2;
            *(uint32_t*)(g_V + o) = pack_h2(sm[e * 65 + 2 * s2], sm[e * 65 + 2 * s2 + 1]);
        }
    }
}

// ---------------------------------------------------------------------------
// attn: persistent work-queue flash attention, mixed-dtype QK:
//   cos/sin (d=128): bf16 3-product (192 MMA/tile, 17.5 cyc each)
//   gate   (d=64) : f16 single    ( 32 MMA/tile, 30 cyc each)
// AV: f16 single (32 MMA/tile). cp.async pipelined (R8/R12 structure).
// ---------------------------------------------------------------------------
__global__ __launch_bounds__(128)
void attn_kernel(const float* __restrict__ mask, const float* __restrict__ keylen,
                 float* __restrict__ out) {
    extern __shared__ char smraw[];
    __nv_bfloat16* sKhi = (__nv_bfloat16*)smraw;                 // [64][KSTR]
    __nv_bfloat16* sKlo = sKhi + 64 * KSTR;
    __half* sKg = (__half*)(sKlo + 64 * KSTR);                   // [64][GSTR]
    __half* sV  = sKg + 64 * GSTR;                               // [2][64][GSTR]

    const int tid  = threadIdx.x;
    const int w    = tid >> 5;
    const int lane = tid & 31;
    const int g    = lane >> 2, t = lane & 3;

    const uint32_t bKhi = smem_u32(sKhi);
    const uint32_t bKlo = smem_u32(sKlo);
    const uint32_t bKg  = smem_u32(sKg);
    const uint32_t bV   = smem_u32(sV);

    unsigned item = blockIdx.x;
    while (item < NITEMS) {
        const int nh = (int)(item / NTILE);
        const int lt = (int)(item % NTILE);
        const int nb = nh >> 3, h = nh & 7;
        const int l0 = lt * BQ;
        const int row0 = l0 + w * 16 + g;

        const uint4* gKhiB = (const uint4*)(g_Khi + (size_t)nh * LL * DD_CS);
        const uint4* gKloB = (const uint4*)(g_Klo + (size_t)nh * LL * DD_CS);
        const uint4* gKgB  = (const uint4*)(g_Kg  + (size_t)nh * LL * DD_G);

        // issue cp.async group for tile it2 (K single buf, V buf vb)
        auto issue_tile = [&](int it2, int vb) {
            const uint4* gH = gKhiB + (size_t)it2 * 64 * DD_CS / 8;
            const uint4* gL = gKloB + (size_t)it2 * 64 * DD_CS / 8;
            #pragma unroll
            for (int i = 0; i < 8; i++) {                  // 1024 uint4 each
                int idx = tid + i * 128;
                int r = idx / 16, c = idx % 16;
                uint32_t off = (uint32_t)(r * KSTR + c * 8) * 2u;
                CP16(bKhi + off, gH + idx);
                CP16(bKlo + off, gL + idx);
            }
            const uint4* gG = gKgB + (size_t)it2 * 64 * DD_G / 8;
            #pragma unroll
            for (int i = 0; i < 4; i++) {                  // 512 uint4
                int idx = tid + i * 128;
                int r = idx / 8, c = idx % 8;
                uint32_t off = (uint32_t)(r * GSTR + c * 8) * 2u;
                CP16(bKg + off, gG + idx);
            }
            #pragma unroll
            for (int i = 0; i < 4; i++) {                  // V 512 uint4
                int idx = tid + i * 128;
                int r = idx / 8, c = idx % 8;
                size_t go = ((size_t)nh * EE + r) * LL + it2 * 64 + c * 8;
                uint32_t off = (uint32_t)(vb * 64 * GSTR + r * GSTR + c * 8) * 2u;
                CP16(bV + off, (const uint4*)(g_V + go));
            }
        };

        issue_tile(0, 0);
        CP_COMMIT();

        // ---- Q fragments (register resident for this item) ----
        uint32_t aQh[8][4], aQl[8][4], aQg[4][4];
        {
            const __nv_bfloat16* qh = g_Qhi + ((size_t)nh * LL + row0) * DD_CS;
            const __nv_bfloat16* ql = g_Qlo + ((size_t)nh * LL + row0) * DD_CS;
            #pragma unroll
            for (int c = 0; c < 8; c++) {
                int d0 = c * 16 + 2 * t;
                aQh[c][0] = *(const uint32_t*)(qh + d0);
                aQh[c][1] = *(const uint32_t*)(qh + 8 * DD_CS + d0);
                aQh[c][2] = *(const uint32_t*)(qh + d0 + 8);
                aQh[c][3] = *(const uint32_t*)(qh + 8 * DD_CS + d0 + 8);
                aQl[c][0] = *(const uint32_t*)(ql + d0);
                aQl[c][1] = *(const uint32_t*)(ql + 8 * DD_CS + d0);
                aQl[c][2] = *(const uint32_t*)(ql + d0 + 8);
                aQl[c][3] = *(const uint32_t*)(ql + 8 * DD_CS + d0 + 8);
            }
            const __half* qg = g_Qg + ((size_t)nh * LL + row0) * DD_G;
            #pragma unroll
            for (int c = 0; c < 4; c++) {
                int d0 = c * 16 + 2 * t;
                aQg[c][0] = *(const uint32_t*)(qg + d0);
                aQg[c][1] = *(const uint32_t*)(qg + 8 * DD_G + d0);
                aQg[c][2] = *(const uint32_t*)(qg + d0 + 8);
                aQg[c][3] = *(const uint32_t*)(qg + 8 * DD_G + d0 + 8);
            }
        }

        float O[8][4];
        #pragma unroll
        for (int n = 0; n < 8; n++)
            #pragma unroll
            for (int j = 0; j < 4; j++) O[n][j] = 0.f;
        float m0 = -CUDART_INF_F, m1 = -CUDART_INF_F, ls0 = 0.f, ls1 = 0.f;

        const float* mrow0b = mask + (size_t)row0 * LL;
        const float* mrow1b = mrow0b + 8 * LL;
        const float* klb    = keylen + (size_t)nb * LL;

        for (int it = 0; it < NTILE; it++) {
            CP_WAIT0();
            __syncthreads();

            float S[8][4];
            #pragma unroll
            for (int n = 0; n < 8; n++)
                #pragma unroll
                for (int j = 0; j < 4; j++) S[n][j] = 0.f;

            // ---- gate channel: f16 single product (4 chunks) ----
            #pragma unroll
            for (int c = 0; c < 4; c++) {
                uint32_t bg[8][2];
                #pragma unroll
                for (int n = 0; n < 8; n++) {
                    const __half* kg = sKg + (n * 8 + g) * GSTR + 2 * t + c * 16;
                    bg[n][0] = *(const uint32_t*)(kg);
                    bg[n][1] = *(const uint32_t*)(kg + 8);
                }
                #pragma unroll
                for (int n = 0; n < 8; n++) mma_f16(S[n], aQg[c], bg[n][0], bg[n][1]);
            }

            // ---- cos/sin channels: bf16 3-product (8 chunks) ----
            #pragma unroll
            for (int c = 0; c < 8; c++) {
                uint32_t bh[8][2], bl[8][2];
                #pragma unroll
                for (int n = 0; n < 8; n++) {
                    const __nv_bfloat16* kh = sKhi + (n * 8 + g) * KSTR + 2 * t + c * 16;
                    const __nv_bfloat16* kl = sKlo + (n * 8 + g) * KSTR + 2 * t + c * 16;
                    bh[n][0] = *(const uint32_t*)(kh);
                    bh[n][1] = *(const uint32_t*)(kh + 8);
                    bl[n][0] = *(const uint32_t*)(kl);
                    bl[n][1] = *(const uint32_t*)(kl + 8);
                }
                #pragma unroll
                for (int n = 0; n < 8; n++) mma_bf16(S[n], aQh[c], bh[n][0], bh[n][1]);
                #pragma unroll
                for (int n = 0; n < 8; n++) mma_bf16(S[n], aQh[c], bl[n][0], bl[n][1]);
                #pragma unroll
                for (int n = 0; n < 8; n++) mma_bf16(S[n], aQl[c], bh[n][0], bh[n][1]);
            }
            __syncthreads();   // all warps done reading K smem

            if (it + 1 < NTILE) issue_tile(it + 1, (it + 1) & 1);
            CP_COMMIT();

            // ---- bias: 0.125 * (mask + keylen) ----
            {
                const float* mr0 = mrow0b + it * 64;
                const float* mr1 = mrow1b + it * 64;
                const float* kl  = klb + it * 64;
                #pragma unroll
                for (int n = 0; n < 8; n++) {
                    int sc = n * 8 + 2 * t;
                    float2 a0 = *(const float2*)(mr0 + sc);
                    float2 a1 = *(const float2*)(mr1 + sc);
                    float2 kk = *(const float2*)(kl + sc);
                    S[n][0] += 0.125f * (a0.x + kk.x);
                    S[n][1] += 0.125f * (a0.y + kk.y);
                    S[n][2] += 0.125f * (a1.x + kk.x);
                    S[n][3] += 0.125f * (a1.y + kk.y);
                }
            }

            // ---- online softmax (rows quad-local) ----
            float mx0 = S[0][0], mx1 = S[0][2];
            #pragma unroll
            for (int n = 0; n < 8; n++) {
                mx0 = fmaxf(mx0, fmaxf(S[n][0], S[n][1]));
                mx1 = fmaxf(mx1, fmaxf(S[n][2], S[n][3]));
            }
            mx0 = fmaxf(mx0, __shfl_xor_sync(0xffffffffu, mx0, 1));
            mx0 = fmaxf(mx0, __shfl_xor_sync(0xffffffffu, mx0, 2));
            mx1 = fmaxf(mx1, __shfl_xor_sync(0xffffffffu, mx1, 1));
            mx1 = fmaxf(mx1, __shfl_xor_sync(0xffffffffu, mx1, 2));
            float m0n = fmaxf(m0, mx0), m1n = fmaxf(m1, mx1);
            float c0 = __expf(m0 - m0n), c1 = __expf(m1 - m1n);
            m0 = m0n; m1 = m1n;
            float s0 = 0.f, s1 = 0.f;
            #pragma unroll
            for (int n = 0; n < 8; n++) {
                S[n][0] = __expf(S[n][0] - m0n);
                S[n][1] = __expf(S[n][1] - m0n);
                S[n][2] = __expf(S[n][2] - m1n);
                S[n][3] = __expf(S[n][3] - m1n);
                s0 += S[n][0] + S[n][1];
                s1 += S[n][2] + S[n][3];
                O[n][0] *= c0; O[n][1] *= c0;
                O[n][2] *= c1; O[n][3] *= c1;
            }
            s0 += __shfl_xor_sync(0xffffffffu, s0, 1);
            s0 += __shfl_xor_sync(0xffffffffu, s0, 2);
            s1 += __shfl_xor_sync(0xffffffffu, s1, 1);
            s1 += __shfl_xor_sync(0xffffffffu, s1, 2);
            ls0 = ls0 * c0 + s0;
            ls1 = ls1 * c1 + s1;

            // ---- P -> fp16 A-fragments (single product) ----
            uint32_t ph[4][4];
            #pragma unroll
            for (int kc = 0; kc < 4; kc++) {
                ph[kc][0] = pack_h2(S[2*kc][0],   S[2*kc][1]);
                ph[kc][1] = pack_h2(S[2*kc][2],   S[2*kc][3]);
                ph[kc][2] = pack_h2(S[2*kc+1][0], S[2*kc+1][1]);
                ph[kc][3] = pack_h2(S[2*kc+1][2], S[2*kc+1][3]);
            }

            // ---- O += P V : kc outer, staged V frags, single fp16 product ----
            const __half* vb = sV + (it & 1) * 64 * GSTR;
            #pragma unroll
            for (int kc = 0; kc < 4; kc++) {
                uint32_t vh[8][2];
                #pragma unroll
                for (int n = 0; n < 8; n++) {
                    const __half* vhp = vb + (n * 8 + g) * GSTR + 2 * t + kc * 16;
                    vh[n][0] = *(const uint32_t*)(vhp);
                    vh[n][1] = *(const uint32_t*)(vhp + 8);
                }
                #pragma unroll
                for (int n = 0; n < 8; n++) mma_f16(O[n], ph[kc], vh[n][0], vh[n][1]);
            }
        }

        // ---- epilogue for this item ----
        float inv0 = 1.0f / ls0, inv1 = 1.0f / ls1;
        float* o0 = out + ((size_t)(nb * LL + row0) * HH + h) * EE;
        float* o1 = o0 + 8 * HH * EE;
        #pragma unroll
        for (int n = 0; n < 8; n++) {
            int e = n * 8 + 2 * t;
            *(float2*)(o0 + e) = make_float2(O[n][0] * inv0, O[n][1] * inv0);
            *(float2*)(o1 + e) = make_float2(O[n][2] * inv1, O[n][3] * inv1);
        }

        // ---- next work item ----
        __shared__ unsigned s_item;
        __syncthreads();
        if (tid == 0) s_item = atomicAdd(&g_ctr, 1u);
        __syncthreads();
        item = s_item;
    }
}

// ---------------------------------------------------------------------------
extern "C" void kernel_launch(void* const* d_in, const int* in_sizes, int n_in,
                              void* d_out, int out_size) {
    const float* queries = (const float*)d_in[0];
    const float* keys    = (const float*)d_in[1];
    const float* values  = (const float*)d_in[2];
    const float* mask    = (const float*)d_in[3];
    const float* keylen  = (const float*)d_in[4];
    const float* freqs   = (const float*)d_in[5];
    const float* offsets = (const float*)d_in[6];
    const float* gains   = (const float*)d_in[7];
    const float* gate    = (const float*)d_in[8];
    float* out = (float*)d_out;

    prep_kernel<<<dim3(48 + NTILE, NH), 256>>>(queries, keys, values,
                                               freqs, offsets, gains, gate);

    // smem: Khi+Klo (2*64*136*2) + Kg (64*72*2) + V double (2*64*72*2)
    const int smem = 2 * 64 * KSTR * 2 + 64 * GSTR * 2 + 2 * 64 * GSTR * 2;   // 62464 B
    cudaFuncSetAttribute(attn_kernel, cudaFuncAttributeMaxDynamicSharedMemorySize, smem);
    attn_kernel<<<GRID_ATTN, 128, smem>>>(mask, keylen, out);
}

// round 16
// speedup vs baseline: 1.5230x; 1.2387x over previous
#include <cuda_runtime.h>
#include <cuda_fp16.h>
#include <math_constants.h>
#include <cstdint>

#define LL 768
#define HH 8
#define EE 64
#define NH 32
#define DD 192
#define BQ 64
#define NTILE 12
#define NITEMS 384          // 12 l-tiles x 32 nh
#define GRID_ATTN 304
#define KSTR 200            // f16 elems per K smem row (400B ≡ 16 mod 128 -> conflict-free)
#define VSTR 72             // f16 elems per V^T smem row

// ---------------- scratch (device globals; no allocs) ----------------
// d-layout: d = e for gate channel (0..63); d = 64+2e (cos), 65+2e (sin).
__device__ __half        g_Q[(size_t)NH * LL * DD];     // Q' fp16
__device__ __half        g_K[(size_t)NH * LL * DD];     // K' fp16
__device__ __half        g_V[(size_t)NH * EE * LL];     // V^T fp16 [nh][e][s]
__device__ unsigned int  g_ctr;

// m16n8k16 row.col fp16 MMA, f32 accumulate
__device__ __forceinline__ void mma_f16(float* c, const uint32_t* a, uint32_t b0, uint32_t b1) {
    asm volatile("mma.sync.aligned.m16n8k16.row.col.f32.f16.f16.f32 "
                 "{%0,%1,%2,%3}, {%4,%5,%6,%7}, {%8,%9}, {%0,%1,%2,%3};"
                 : "+f"(c[0]), "+f"(c[1]), "+f"(c[2]), "+f"(c[3])
                 : "r"(a[0]), "r"(a[1]), "r"(a[2]), "r"(a[3]), "r"(b0), "r"(b1));
}

__device__ __forceinline__ uint32_t smem_u32(const void* p) {
    uint32_t a;
    asm("{ .reg .u64 t; cvta.to.shared.u64 t, %1; cvt.u32.u64 %0, t; }" : "=r"(a) : "l"(p));
    return a;
}

#define CP16(dst, src) asm volatile("cp.async.cg.shared.global [%0], [%1], 16;" :: "r"(dst), "l"(src))
#define CP_COMMIT()    asm volatile("cp.async.commit_group;" ::: "memory")
#define CP_WAIT0()     asm volatile("cp.async.wait_group 0;" ::: "memory")

__device__ __forceinline__ uint32_t pack_h2(float x, float y) {
    __half2 h = __floats2half2_rn(x, y);
    return *(uint32_t*)&h;
}

// ---------------------------------------------------------------------------
// prep (fused): blockIdx.x < 48 -> Q'/K' fp16 build; else -> V transpose.
// ---------------------------------------------------------------------------
__global__ void prep_kernel(const float* __restrict__ q, const float* __restrict__ k,
                            const float* __restrict__ values,
                            const float* __restrict__ freqs, const float* __restrict__ offsets,
                            const float* __restrict__ gains, const float* __restrict__ gate) {
    const int nh = blockIdx.y;
    const int n = nh >> 3, h = nh & 7;

    if (blockIdx.x < 48) {
        if (blockIdx.x == 0 && blockIdx.y == 0 && threadIdx.x == 0)
            g_ctr = GRID_ATTN;                // seed attn work queue

        int e  = threadIdx.x & 63;
        int j  = threadIdx.x >> 6;            // 0..3
        int l0 = blockIdx.x * 16 + j * 4;
        int he = h * 64 + e;

        float fr  = freqs[he];
        float f   = 0.5f / (1.0f + __expf(-fr));
        float off = offsets[he];
        float gn  = gains[he];
        float g   = (gn > 8.0f) ? gn : __logf(1.0f + __expf(gn));
        float gt  = gate[he];
        float c   = (1.0f - gt) * g * g;

        float lf    = (float)l0;
        float fl    = f * lf;
        float resid = fmaf(f, lf, -fl);
        float frac  = (fl - floorf(fl)) + resid;
        const float TWO_PI = 6.28318530717958647692f;
        float phk   = TWO_PI * frac;
        float argq  = phk + off;
        float cq = __cosf(argq), sq = __sinf(argq);
        float ck = __cosf(phk),  sk = __sinf(phk);
        float dph = TWO_PI * f;
        float cF = __cosf(dph), sF = __sinf(dph);

        #pragma unroll
        for (int dl = 0; dl < 4; dl++) {
            int l = l0 + dl;
            size_t qi = ((size_t)(n * LL + l) * HH + h) * EE + e;
            float qv = q[qi] * 0.125f;        // softmax temp folded into Q'
            float kv = k[qi];

            size_t base = ((size_t)nh * LL + l) * DD;
            // gate channel (d = e)
            g_Q[base + e] = __float2half_rn(qv * gt);
            g_K[base + e] = __float2half_rn(kv);
            // cos/sin channels (d = 64+2e, 65+2e)
            float qc = qv * c;
            *(uint32_t*)(g_Q + base + 64 + 2 * e) = pack_h2(qc * cq, qc * sq);
            *(uint32_t*)(g_K + base + 64 + 2 * e) = pack_h2(kv * ck, kv * sk);

            float cq2 = cq * cF - sq * sF, sq2 = sq * cF + cq * sF;
            float ck2 = ck * cF - sk * sF, sk2 = sk * cF + ck * sF;
            cq = cq2; sq = sq2; ck = ck2; sk = sk2;
        }
    } else {
        __shared__ float sm[64 * 65];
        int t = blockIdx.x - 48;
        int s0 = t * 64;

        #pragma unroll
        for (int i = 0; i < 16; i++) {
            int idx = threadIdx.x + i * 256;
            int r = idx >> 6, e = idx & 63;
            sm[e * 65 + r] = values[((size_t)(n * LL + s0 + r) * HH + h) * EE + e];
        }
        __syncthreads();

        #pragma unroll
        for (int i = 0; i < 8; i++) {
            int pid = threadIdx.x + i * 256;
            int e = pid >> 5, s2 = pid & 31;
            size_t o = ((size_t)nh * EE + e) * LL + s0 + 2 * s2;
            *(uint32_t*)(g_V + o) = pack_h2(sm[e * 65 + 2 * s2], sm[e * 65 + 2 * s2 + 1]);
        }
    }
}

// ---------------------------------------------------------------------------
// attn: persistent work-queue flash attention, uniform fp16 single-product.
// QK: 12 k16-chunks x 8 n = 96 MMA/tile. AV: 32 MMA/tile.
// cp.async pipelined exactly as the proven R8/R12/R15 structure.
// ---------------------------------------------------------------------------
__global__ __launch_bounds__(128)
void attn_kernel(const float* __restrict__ mask, const float* __restrict__ keylen,
                 float* __restrict__ out) {
    extern __shared__ __half smem[];
    __half* sK = smem;                                // [64][KSTR]
    __half* sV = smem + 64 * KSTR;                    // [2][64][VSTR]

    const int tid  = threadIdx.x;
    const int w    = tid >> 5;
    const int lane = tid & 31;
    const int g    = lane >> 2, t = lane & 3;

    const uint32_t bK = smem_u32(sK);
    const uint32_t bV = smem_u32(sV);

    unsigned item = blockIdx.x;
    while (item < NITEMS) {
        const int nh = (int)(item / NTILE);
        const int lt = (int)(item % NTILE);
        const int nb = nh >> 3, h = nh & 7;
        const int l0 = lt * BQ;
        const int row0 = l0 + w * 16 + g;

        const uint4* gKB = (const uint4*)(g_K + (size_t)nh * LL * DD);

        // issue cp.async group for tile it2 (K single buf, V buf vb)
        auto issue_tile = [&](int it2, int vb) {
            const uint4* gKt = gKB + (size_t)it2 * 64 * DD / 8;
            #pragma unroll
            for (int i = 0; i < 12; i++) {
                int idx = tid + i * 128;
                int r = idx / 24, c = idx % 24;
                uint32_t off = (uint32_t)(r * KSTR + c * 8) * 2u;
                CP16(bK + off, gKt + idx);
            }
            #pragma unroll
            for (int i = 0; i < 4; i++) {
                int idx = tid + i * 128;
                int r = idx / 8, c = idx % 8;
                size_t go = ((size_t)nh * EE + r) * LL + it2 * 64 + c * 8;
                uint32_t off = (uint32_t)(vb * 64 * VSTR + r * VSTR + c * 8) * 2u;
                CP16(bV + off, (const uint4*)(g_V + go));
            }
        };

        issue_tile(0, 0);
        CP_COMMIT();

        // ---- Q fragments (fp16; register resident for this item) ----
        uint32_t aQ[12][4];
        {
            const __half* qp = g_Q + ((size_t)nh * LL + row0) * DD;
            #pragma unroll
            for (int c = 0; c < 12; c++) {
                int d0 = c * 16 + 2 * t;
                aQ[c][0] = *(const uint32_t*)(qp + d0);
                aQ[c][1] = *(const uint32_t*)(qp + 8 * DD + d0);
                aQ[c][2] = *(const uint32_t*)(qp + d0 + 8);
                aQ[c][3] = *(const uint32_t*)(qp + 8 * DD + d0 + 8);
            }
        }

        float O[8][4];
        #pragma unroll
        for (int n = 0; n < 8; n++)
            #pragma unroll
            for (int j = 0; j < 4; j++) O[n][j] = 0.f;
        float m0 = -CUDART_INF_F, m1 = -CUDART_INF_F, ls0 = 0.f, ls1 = 0.f;

        const float* mrow0b = mask + (size_t)row0 * LL;
        const float* mrow1b = mrow0b + 8 * LL;
        const float* klb    = keylen + (size_t)nb * LL;

        for (int it = 0; it < NTILE; it++) {
            CP_WAIT0();
            __syncthreads();

            // ---- S = Q' K'^T : c outer, staged B frags, single f16 product ----
            float S[8][4];
            #pragma unroll
            for (int n = 0; n < 8; n++)
                #pragma unroll
                for (int j = 0; j < 4; j++) S[n][j] = 0.f;

            #pragma unroll
            for (int c = 0; c < 12; c++) {
                uint32_t bh[8][2];
                #pragma unroll
                for (int n = 0; n < 8; n++) {
                    const __half* kp = sK + (n * 8 + g) * KSTR + 2 * t + c * 16;
                    bh[n][0] = *(const uint32_t*)(kp);
                    bh[n][1] = *(const uint32_t*)(kp + 8);
                }
                #pragma unroll
                for (int n = 0; n < 8; n++) mma_f16(S[n], aQ[c], bh[n][0], bh[n][1]);
            }
            __syncthreads();   // all warps done reading K smem

            if (it + 1 < NTILE) issue_tile(it + 1, (it + 1) & 1);
            CP_COMMIT();

            // ---- bias: 0.125 * (mask + keylen) ----
            {
                const float* mr0 = mrow0b + it * 64;
                const float* mr1 = mrow1b + it * 64;
                const float* kl  = klb + it * 64;
                #pragma unroll
                for (int n = 0; n < 8; n++) {
                    int sc = n * 8 + 2 * t;
                    float2 a0 = *(const float2*)(mr0 + sc);
                    float2 a1 = *(const float2*)(mr1 + sc);
                    float2 kk = *(const float2*)(kl + sc);
                    S[n][0] += 0.125f * (a0.x + kk.x);
                    S[n][1] += 0.125f * (a0.y + kk.y);
                    S[n][2] += 0.125f * (a1.x + kk.x);
                    S[n][3] += 0.125f * (a1.y + kk.y);
                }
            }

            // ---- online softmax (rows quad-local) ----
            float mx0 = S[0][0], mx1 = S[0][2];
            #pragma unroll
            for (int n = 0; n < 8; n++) {
                mx0 = fmaxf(mx0, fmaxf(S[n][0], S[n][1]));
                mx1 = fmaxf(mx1, fmaxf(S[n][2], S[n][3]));
            }
            mx0 = fmaxf(mx0, __shfl_xor_sync(0xffffffffu, mx0, 1));
            mx0 = fmaxf(mx0, __shfl_xor_sync(0xffffffffu, mx0, 2));
            mx1 = fmaxf(mx1, __shfl_xor_sync(0xffffffffu, mx1, 1));
            mx1 = fmaxf(mx1, __shfl_xor_sync(0xffffffffu, mx1, 2));
            float m0n = fmaxf(m0, mx0), m1n = fmaxf(m1, mx1);
            float c0 = __expf(m0 - m0n), c1 = __expf(m1 - m1n);
            m0 = m0n; m1 = m1n;
            float s0 = 0.f, s1 = 0.f;
            #pragma unroll
            for (int n = 0; n < 8; n++) {
                S[n][0] = __expf(S[n][0] - m0n);
                S[n][1] = __expf(S[n][1] - m0n);
                S[n][2] = __expf(S[n][2] - m1n);
                S[n][3] = __expf(S[n][3] - m1n);
                s0 += S[n][0] + S[n][1];
                s1 += S[n][2] + S[n][3];
                O[n][0] *= c0; O[n][1] *= c0;
                O[n][2] *= c1; O[n][3] *= c1;
            }
            s0 += __shfl_xor_sync(0xffffffffu, s0, 1);
            s0 += __shfl_xor_sync(0xffffffffu, s0, 2);
            s1 += __shfl_xor_sync(0xffffffffu, s1, 1);
            s1 += __shfl_xor_sync(0xffffffffu, s1, 2);
            ls0 = ls0 * c0 + s0;
            ls1 = ls1 * c1 + s1;

            // ---- P -> fp16 A-fragments (single product) ----
            uint32_t ph[4][4];
            #pragma unroll
            for (int kc = 0; kc < 4; kc++) {
                ph[kc][0] = pack_h2(S[2*kc][0],   S[2*kc][1]);
                ph[kc][1] = pack_h2(S[2*kc][2],   S[2*kc][3]);
                ph[kc][2] = pack_h2(S[2*kc+1][0], S[2*kc+1][1]);
                ph[kc][3] = pack_h2(S[2*kc+1][2], S[2*kc+1][3]);
            }

            // ---- O += P V : kc outer, staged V frags, single fp16 product ----
            const __half* vb = sV + (it & 1) * 64 * VSTR;
            #pragma unroll
            for (int kc = 0; kc < 4; kc++) {
                uint32_t vh[8][2];
                #pragma unroll
                for (int n = 0; n < 8; n++) {
                    const __half* vhp = vb + (n * 8 + g) * VSTR + 2 * t + kc * 16;
                    vh[n][0] = *(const uint32_t*)(vhp);
                    vh[n][1] = *(const uint32_t*)(vhp + 8);
                }
                #pragma unroll
                for (int n = 0; n < 8; n++) mma_f16(O[n], ph[kc], vh[n][0], vh[n][1]);
            }
        }

        // ---- epilogue for this item ----
        float inv0 = 1.0f / ls0, inv1 = 1.0f / ls1;
        float* o0 = out + ((size_t)(nb * LL + row0) * HH + h) * EE;
        float* o1 = o0 + 8 * HH * EE;
        #pragma unroll
        for (int n = 0; n < 8; n++) {
            int e = n * 8 + 2 * t;
            *(float2*)(o0 + e) = make_float2(O[n][0] * inv0, O[n][1] * inv0);
            *(float2*)(o1 + e) = make_float2(O[n][2] * inv1, O[n][3] * inv1);
        }

        // ---- next work item ----
        __shared__ unsigned s_item;
        __syncthreads();
        if (tid == 0) s_item = atomicAdd(&g_ctr, 1u);
        __syncthreads();
        item = s_item;
    }
}

// ---------------------------------------------------------------------------
extern "C" void kernel_launch(void* const* d_in, const int* in_sizes, int n_in,
                              void* d_out, int out_size) {
    const float* queries = (const float*)d_in[0];
    const float* keys    = (const float*)d_in[1];
    const float* values  = (const float*)d_in[2];
    const float* mask    = (const float*)d_in[3];
    const float* keylen  = (const float*)d_in[4];
    const float* freqs   = (const float*)d_in[5];
    const float* offsets = (const float*)d_in[6];
    const float* gains   = (const float*)d_in[7];
    const float* gate    = (const float*)d_in[8];
    float* out = (float*)d_out;

    prep_kernel<<<dim3(48 + NTILE, NH), 256>>>(queries, keys, values,
                                               freqs, offsets, gains, gate);

    const int smem = (64 * KSTR + 2 * 64 * VSTR) * 2;   // 44032 B
    cudaFuncSetAttribute(attn_kernel, cudaFuncAttributeMaxDynamicSharedMemorySize, smem);
    attn_kernel<<<GRID_ATTN, 128, smem>>>(mask, keylen, out);
}